// round 8
// baseline (speedup 1.0000x reference)
#include <cuda_runtime.h>
#include <cuda_bf16.h>
#include <cstdint>
#include <math.h>

// Problem constants
#define B 8
#define S 1025
#define E 1408
#define H 16
#define D 88
#define D2 44
#define M_ROWS (B * S)          // 8200

// ---------------------------------------------------------------------------
// Scratch (allocation-free: __device__ globals)
// ---------------------------------------------------------------------------
__device__ float g_q[(size_t)M_ROWS * E];
__device__ float g_k[(size_t)M_ROWS * E];
__device__ float g_v[(size_t)M_ROWS * E];
__device__ float g_attn[(size_t)M_ROWS * E];
__device__ __nv_bfloat16 g_ahi[(size_t)M_ROWS * E];
__device__ __nv_bfloat16 g_alo[(size_t)M_ROWS * E];
__device__ __nv_bfloat16 g_whi[(size_t)E * E];
__device__ __nv_bfloat16 g_wlo[(size_t)E * E];

// ---------------------------------------------------------------------------
// Split fp32 -> (hi, lo) bf16 pair.  x = hi + lo + O(2^-18 x)
// ---------------------------------------------------------------------------
__global__ __launch_bounds__(256)
void split_bf16(const float* __restrict__ x,
                __nv_bfloat16* __restrict__ hi,
                __nv_bfloat16* __restrict__ lo,
                size_t n)
{
    size_t i = ((size_t)blockIdx.x * 256 + threadIdx.x) * 4;
    if (i >= n) return;
    float4 v = *(const float4*)(x + i);
    __nv_bfloat16 h0 = __float2bfloat16(v.x);
    __nv_bfloat16 h1 = __float2bfloat16(v.y);
    __nv_bfloat16 h2 = __float2bfloat16(v.z);
    __nv_bfloat16 h3 = __float2bfloat16(v.w);
    __nv_bfloat16 l0 = __float2bfloat16(v.x - __bfloat162float(h0));
    __nv_bfloat16 l1 = __float2bfloat16(v.y - __bfloat162float(h1));
    __nv_bfloat16 l2 = __float2bfloat16(v.z - __bfloat162float(h2));
    __nv_bfloat16 l3 = __float2bfloat16(v.w - __bfloat162float(h3));
    __nv_bfloat162* hp = (__nv_bfloat162*)(hi + i);
    __nv_bfloat162* lp = (__nv_bfloat162*)(lo + i);
    hp[0] = __nv_bfloat162(h0, h1);
    hp[1] = __nv_bfloat162(h2, h3);
    lp[0] = __nv_bfloat162(l0, l1);
    lp[1] = __nv_bfloat162(l2, l3);
}

// ---------------------------------------------------------------------------
// HMMA / packed-f32 helpers (baseline PTX — compiles for plain sm_103)
// ---------------------------------------------------------------------------
__device__ __forceinline__ void mma16816(float* c, const uint32_t* a,
                                         const uint32_t* b)
{
    asm volatile(
        "mma.sync.aligned.m16n8k16.row.col.f32.bf16.bf16.f32 "
        "{%0,%1,%2,%3}, {%4,%5,%6,%7}, {%8,%9}, {%0,%1,%2,%3};\n"
        : "+f"(c[0]), "+f"(c[1]), "+f"(c[2]), "+f"(c[3])
        : "r"(a[0]), "r"(a[1]), "r"(a[2]), "r"(a[3]),
          "r"(b[0]), "r"(b[1]));
}

__device__ __forceinline__ void ldsm4(uint32_t* r, uint32_t addr) {
    asm volatile(
        "ldmatrix.sync.aligned.m8n8.x4.shared.b16 {%0,%1,%2,%3}, [%4];\n"
        : "=r"(r[0]), "=r"(r[1]), "=r"(r[2]), "=r"(r[3]) : "r"(addr));
}

__device__ __forceinline__ void cp16(uint32_t dst, const void* src, bool valid) {
    uint64_t g = __cvta_generic_to_global(src);
    uint32_t sz = valid ? 16u : 0u;
    asm volatile("cp.async.cg.shared.global [%0], [%1], 16, %2;\n"
                 :: "r"(dst), "l"(g), "r"(sz));
}

typedef unsigned long long ull;

__device__ __forceinline__ ull ffma2(ull a, ull b, ull c) {
    ull d;
    asm("fma.rn.f32x2 %0, %1, %2, %3;" : "=l"(d) : "l"(a), "l"(b), "l"(c));
    return d;
}
__device__ __forceinline__ ull fmul2(ull a, ull b) {
    ull d;
    asm("mul.rn.f32x2 %0, %1, %2;" : "=l"(d) : "l"(a), "l"(b));
    return d;
}
__device__ __forceinline__ ull pk2(float a, float b) {
    ull r;
    asm("mov.b64 %0, {%1,%2};" : "=l"(r) : "f"(a), "f"(b));
    return r;
}
__device__ __forceinline__ void upk2(ull v, float& a, float& b) {
    asm("mov.b64 {%0,%1}, %2;" : "=f"(a), "=f"(b) : "l"(v));
}

// ---------------------------------------------------------------------------
// HMMA GEMM: C[m][n] = sum_k A[m][k]*W[n][k] + bias[n], optional RoPE.
// Split-bf16: D += Ah*Wh + Ah*Wl + Al*Wh.
// CTA tile 128x128, BK=32, 8 warps (4x2), warp tile 32x64.
// Fragments via ldmatrix.x4 (pitch 80B rows -> conflict-free).
// ---------------------------------------------------------------------------
#define BKT 32
#define NSTG (E / BKT)            // 44
#define PITCH 40                  // bf16 elements per smem row
#define ARR_B (128 * PITCH * 2)   // 10240 B per array
#define STAGE_B (4 * ARR_B)       // Ah, Al, Wh, Wl = 40960 B
#define GEMM_SMEM (2 * STAGE_B)   // 81920 B

extern __shared__ char dsm[];

__device__ __forceinline__ void stage_loads(
    uint32_t smem, int s, int m0, int n0, int Mdim,
    const __nv_bfloat16* Ahi, const __nv_bfloat16* Alo,
    const __nv_bfloat16* Whi, const __nv_bfloat16* Wlo)
{
    const int tid = threadIdx.x;
    const int k0 = s * BKT;
    const uint32_t base = smem + (uint32_t)(s & 1) * STAGE_B;
#pragma unroll
    for (int i = 0; i < 8; i++) {
        int c = tid + i * 256;            // 0..2047
        int arr = c >> 9;                 // 0..3
        int rem = c & 511;
        int row = rem >> 2;               // 0..127
        int ch  = rem & 3;                // 16B chunk within 64B row
        uint32_t dst = base + (uint32_t)arr * ARR_B
                     + (uint32_t)row * (PITCH * 2) + (uint32_t)ch * 16;
        const __nv_bfloat16* src;
        int gr;
        bool valid = true;
        if (arr == 0)      { src = Ahi; gr = m0 + row; valid = gr < Mdim; }
        else if (arr == 1) { src = Alo; gr = m0 + row; valid = gr < Mdim; }
        else if (arr == 2) { src = Whi; gr = n0 + row; }
        else               { src = Wlo; gr = n0 + row; }
        if (!valid) gr = 0;
        cp16(dst, src + (size_t)gr * E + k0 + ch * 8, valid);
    }
    asm volatile("cp.async.commit_group;\n" ::: "memory");
}

__global__ __launch_bounds__(256)
void gemm_tc(const __nv_bfloat16* __restrict__ Ahi,
             const __nv_bfloat16* __restrict__ Alo,
             const __nv_bfloat16* __restrict__ Whi,
             const __nv_bfloat16* __restrict__ Wlo,
             const float* __restrict__ bias,
             const float* __restrict__ fcos,
             const float* __restrict__ fsin,
             float* __restrict__ C,
             int Mdim, int rope)
{
    uint32_t smem = (uint32_t)__cvta_generic_to_shared(dsm);
    const int tid    = threadIdx.x;
    const int wid    = tid >> 5;
    const int lane   = tid & 31;
    const int warp_m = wid & 3;       // 4 warps along M
    const int warp_n = wid >> 2;      // 2 warps along N
    const int g = lane >> 2;          // group id 0..7
    const int t = lane & 3;           // thread in group
    const int lgrp = lane >> 3;       // ldmatrix group 0..3
    const int lrow = lane & 7;        // row within 8x8 matrix
    const int m0 = blockIdx.x * 128;
    const int n0 = blockIdx.y * 128;

    float acc[2][8][4];
#pragma unroll
    for (int mt = 0; mt < 2; mt++)
#pragma unroll
        for (int nt = 0; nt < 8; nt++)
#pragma unroll
            for (int e = 0; e < 4; e++) acc[mt][nt][e] = 0.f;

    stage_loads(smem, 0, m0, n0, Mdim, Ahi, Alo, Whi, Wlo);

    for (int s = 0; s < NSTG; s++) {
        if (s + 1 < NSTG) {
            stage_loads(smem, s + 1, m0, n0, Mdim, Ahi, Alo, Whi, Wlo);
            asm volatile("cp.async.wait_group 1;\n" ::: "memory");
        } else {
            asm volatile("cp.async.wait_group 0;\n" ::: "memory");
        }
        __syncthreads();

        const uint32_t bufb = smem + (uint32_t)(s & 1) * STAGE_B;
        const uint32_t aB  = bufb;
        const uint32_t alB = bufb + ARR_B;
        const uint32_t whB = bufb + 2 * ARR_B;
        const uint32_t wlB = bufb + 3 * ARR_B;

#pragma unroll
        for (int ks = 0; ks < 2; ks++) {
            uint32_t Ah[2][4], Al[2][4];
#pragma unroll
            for (int mt = 0; mt < 2; mt++) {
                uint32_t off = (uint32_t)(warp_m * 32 + mt * 16
                               + (lgrp & 1) * 8 + lrow) * (PITCH * 2)
                               + (uint32_t)ks * 32 + (uint32_t)(lgrp >> 1) * 16;
                ldsm4(Ah[mt], aB + off);
                ldsm4(Al[mt], alB + off);
            }
#pragma unroll
            for (int p = 0; p < 4; p++) {
                uint32_t off = (uint32_t)(warp_n * 64 + p * 16
                               + (lgrp >> 1) * 8 + lrow) * (PITCH * 2)
                               + (uint32_t)ks * 32 + (uint32_t)(lgrp & 1) * 16;
                uint32_t Bh[4], Bl[4];
                ldsm4(Bh, whB + off);
                ldsm4(Bl, wlB + off);
#pragma unroll
                for (int mt = 0; mt < 2; mt++) {
                    mma16816(acc[mt][2 * p],     Ah[mt], &Bh[0]);
                    mma16816(acc[mt][2 * p],     Ah[mt], &Bl[0]);
                    mma16816(acc[mt][2 * p],     Al[mt], &Bh[0]);
                    mma16816(acc[mt][2 * p + 1], Ah[mt], &Bh[2]);
                    mma16816(acc[mt][2 * p + 1], Ah[mt], &Bl[2]);
                    mma16816(acc[mt][2 * p + 1], Al[mt], &Bh[2]);
                }
            }
        }
        __syncthreads();
    }

    // Epilogue: bias + optional RoPE. c0,c1 -> (row, col..col+1); c2,c3 -> row+8.
#pragma unroll
    for (int mt = 0; mt < 2; mt++) {
        const int mA = m0 + warp_m * 32 + mt * 16 + g;
        const int mB = mA + 8;
        const int sA = mA % S;
        const int sB = mB % S;
#pragma unroll
        for (int nt = 0; nt < 8; nt++) {
            const int n = n0 + warp_n * 64 + nt * 8 + t * 2;
            const float b0 = bias[n];
            const float b1 = bias[n + 1];
            float v0 = acc[mt][nt][0] + b0;
            float v1 = acc[mt][nt][1] + b1;
            float v2 = acc[mt][nt][2] + b0;
            float v3 = acc[mt][nt][3] + b1;
            if (rope) {
                const int i0 = (n % D) >> 1;
                float cA = fcos[sA * D2 + i0], snA = fsin[sA * D2 + i0];
                float cB = fcos[sB * D2 + i0], snB = fsin[sB * D2 + i0];
                float t0 = v0 * cA - v1 * snA;
                v1       = v0 * snA + v1 * cA;
                v0 = t0;
                float t2 = v2 * cB - v3 * snB;
                v3       = v2 * snB + v3 * cB;
                v2 = t2;
            }
            if (mA < Mdim) *(float2*)&C[(size_t)mA * E + n] = make_float2(v0, v1);
            if (mB < Mdim) *(float2*)&C[(size_t)mB * E + n] = make_float2(v2, v3);
        }
    }
}

// ---------------------------------------------------------------------------
// Flash attention v3: f32x2-packed, 4 queries/warp (2 pairs), 32-key tiles.
// K/V duplicated (x,x) in smem -> LDS.64 feeds FFMA2 directly.
// Dynamic smem, pitch 98 float2 per row (784B: conflict-free, covers pad).
// ---------------------------------------------------------------------------
#define TK 32
#define NW 8
#define QPW 4
#define AP 98                                     // float2 pitch
#define ATTN_SMEM ((2 * TK * AP + NW * 2 * AP + NW * 2 * TK) * 8)

__global__ __launch_bounds__(256)
void flash_attn(const float* __restrict__ q,
                const float* __restrict__ k,
                const float* __restrict__ v,
                float* __restrict__ out)
{
    float2* K2 = (float2*)dsm;
    float2* V2 = K2 + TK * AP;
    float2* q2 = V2 + TK * AP;
    float2* p2 = q2 + NW * 2 * AP;

    const int bh = blockIdx.y;
    const int b  = bh / H;
    const int h  = bh % H;
    const int warp = threadIdx.x >> 5;
    const int lane = threadIdx.x & 31;
    const int q0 = (blockIdx.x * NW + warp) * QPW;

    const float scale = rsqrtf((float)D);

    // q pairs: q2[(warp*2+p)][d] = (q_{2p}[d], q_{2p+1}[d]) * scale
#pragma unroll
    for (int p = 0; p < 2; p++) {
        float2* qrow = q2 + (warp * 2 + p) * AP;
        int qa = q0 + 2 * p, qb = q0 + 2 * p + 1;
        const float* pa = &q[((size_t)(b * S + (qa < S ? qa : 0))) * E + h * D];
        const float* pb = &q[((size_t)(b * S + (qb < S ? qb : 0))) * E + h * D];
        for (int d = lane; d < D; d += 32) {
            float va = (qa < S) ? pa[d] * scale : 0.f;
            float vb = (qb < S) ? pb[d] * scale : 0.f;
            qrow[d] = make_float2(va, vb);
        }
    }

    float mrun[QPW], lrun[QPW];
#pragma unroll
    for (int qq = 0; qq < QPW; qq++) { mrun[qq] = -1e30f; lrun[qq] = 0.f; }
    ull oo[2][3] = {{0ull, 0ull, 0ull}, {0ull, 0ull, 0ull}};

    // zero V pad columns d=88..97 (read by PV at lane+64)
    for (int idx = threadIdx.x; idx < TK * (AP - D); idx += 256) {
        int r = idx / (AP - D);
        int d = D + idx % (AP - D);
        V2[r * AP + d] = make_float2(0.f, 0.f);
    }

    for (int t0 = 0; t0 < S; t0 += TK) {
        __syncthreads();   // previous tile fully consumed

        // K/V tile load, duplicated lanes: (x,x,y,y) float4 stores
        for (int idx = threadIdx.x; idx < TK * (D / 4); idx += 256) {
            int r  = idx / (D / 4);
            int c4 = idx % (D / 4);
            int key = t0 + r;
            float4 kv, vv;
            if (key < S) {
                size_t base = ((size_t)(b * S + key)) * E + h * D + c4 * 4;
                kv = *(const float4*)&k[base];
                vv = *(const float4*)&v[base];
            } else {
                kv = make_float4(0.f, 0.f, 0.f, 0.f);
                vv = kv;
            }
            float2* kr = K2 + r * AP + c4 * 4;
            float2* vr = V2 + r * AP + c4 * 4;
            *(float4*)(kr)     = make_float4(kv.x, kv.x, kv.y, kv.y);
            *(float4*)(kr + 2) = make_float4(kv.z, kv.z, kv.w, kv.w);
            *(float4*)(vr)     = make_float4(vv.x, vv.x, vv.y, vv.y);
            *(float4*)(vr + 2) = make_float4(vv.z, vv.z, vv.w, vv.w);
        }
        __syncthreads();

        const int key = t0 + lane;
        const bool kin = (key < S);

        // QK: packed dot products (pairs of queries)
        ull s01 = 0ull, s23 = 0ull;
        {
            const float2* kr  = K2 + lane * AP;
            const float2* qa  = q2 + (warp * 2) * AP;
            const float2* qb  = q2 + (warp * 2 + 1) * AP;
#pragma unroll
            for (int c = 0; c < D / 4; c++) {
                ulonglong2 kA = *(const ulonglong2*)(kr + c * 4);
                ulonglong2 kB = *(const ulonglong2*)(kr + c * 4 + 2);
                ulonglong2 a0 = *(const ulonglong2*)(qa + c * 4);
                ulonglong2 a1 = *(const ulonglong2*)(qa + c * 4 + 2);
                ulonglong2 b0 = *(const ulonglong2*)(qb + c * 4);
                ulonglong2 b1 = *(const ulonglong2*)(qb + c * 4 + 2);
                s01 = ffma2(kA.x, a0.x, s01);
                s01 = ffma2(kA.y, a0.y, s01);
                s01 = ffma2(kB.x, a1.x, s01);
                s01 = ffma2(kB.y, a1.y, s01);
                s23 = ffma2(kA.x, b0.x, s23);
                s23 = ffma2(kA.y, b0.y, s23);
                s23 = ffma2(kB.x, b1.x, s23);
                s23 = ffma2(kB.y, b1.y, s23);
            }
        }
        float sc[QPW];
        upk2(s01, sc[0], sc[1]);
        upk2(s23, sc[2], sc[3]);

        // online softmax (scalar fp32, unchanged numerics)
        float pv[QPW], alpha[QPW];
#pragma unroll
        for (int qq = 0; qq < QPW; qq++) {
            float s = kin ? sc[qq] : -1e30f;
            float mt = s;
#pragma unroll
            for (int off = 16; off; off >>= 1)
                mt = fmaxf(mt, __shfl_xor_sync(0xffffffffu, mt, off));
            float mnew = fmaxf(mrun[qq], mt);
            float p = kin ? __expf(s - mnew) : 0.f;
            float ps = p;
#pragma unroll
            for (int off = 16; off; off >>= 1)
                ps += __shfl_xor_sync(0xffffffffu, ps, off);
            alpha[qq] = __expf(mrun[qq] - mnew);
            lrun[qq] = lrun[qq] * alpha[qq] + ps;
            mrun[qq] = mnew;
            pv[qq] = p;
        }
        p2[(warp * 2) * TK + lane]     = make_float2(pv[0], pv[1]);
        p2[(warp * 2 + 1) * TK + lane] = make_float2(pv[2], pv[3]);

        ull aa0 = pk2(alpha[0], alpha[1]);
        ull aa1 = pk2(alpha[2], alpha[3]);
#pragma unroll
        for (int c = 0; c < 3; c++) {
            oo[0][c] = fmul2(oo[0][c], aa0);
            oo[1][c] = fmul2(oo[1][c], aa1);
        }
        __syncwarp();

        // PV: packed accumulation
        {
            const float2* pr0 = p2 + (warp * 2) * TK;
            const float2* pr1 = p2 + (warp * 2 + 1) * TK;
#pragma unroll 8
            for (int j = 0; j < TK; j++) {
                const float2* vr = V2 + j * AP;
                ull v0 = *(const ull*)(vr + lane);
                ull v1 = *(const ull*)(vr + lane + 32);
                ull vx = *(const ull*)(vr + lane + 64);
                ull pp0 = *(const ull*)(pr0 + j);
                ull pp1 = *(const ull*)(pr1 + j);
                oo[0][0] = ffma2(pp0, v0, oo[0][0]);
                oo[0][1] = ffma2(pp0, v1, oo[0][1]);
                oo[0][2] = ffma2(pp0, vx, oo[0][2]);
                oo[1][0] = ffma2(pp1, v0, oo[1][0]);
                oo[1][1] = ffma2(pp1, v1, oo[1][1]);
                oo[1][2] = ffma2(pp1, vx, oo[1][2]);
            }
        }
        __syncwarp();
    }

    // write out
#pragma unroll
    for (int p = 0; p < 2; p++) {
        float o0a, o0b, o1a, o1b, o2a, o2b;
        upk2(oo[p][0], o0a, o0b);
        upk2(oo[p][1], o1a, o1b);
        upk2(oo[p][2], o2a, o2b);
        int qa = q0 + 2 * p, qb = q0 + 2 * p + 1;
        if (qa < S) {
            float inv = 1.f / lrun[2 * p];
            float* op = &out[((size_t)(b * S + qa)) * E + h * D];
            op[lane]      = o0a * inv;
            op[lane + 32] = o1a * inv;
            if (lane < D - 64) op[lane + 64] = o2a * inv;
        }
        if (qb < S) {
            float inv = 1.f / lrun[2 * p + 1];
            float* op = &out[((size_t)(b * S + qb)) * E + h * D];
            op[lane]      = o0b * inv;
            op[lane + 32] = o1b * inv;
            if (lane < D - 64) op[lane + 64] = o2b * inv;
        }
    }
}

// ---------------------------------------------------------------------------
// Launch
// ---------------------------------------------------------------------------
extern "C" void kernel_launch(void* const* d_in, const int* in_sizes, int n_in,
                              void* d_out, int out_size)
{
    const float* hs   = (const float*)d_in[0];
    const float* fcos = (const float*)d_in[1];
    const float* fsin = (const float*)d_in[2];
    const float* Wq   = (const float*)d_in[3];
    const float* bq   = (const float*)d_in[4];
    const float* Wk   = (const float*)d_in[5];
    const float* bk   = (const float*)d_in[6];
    const float* Wv   = (const float*)d_in[7];
    const float* bv   = (const float*)d_in[8];
    const float* Wo   = (const float*)d_in[9];
    const float* bo   = (const float*)d_in[10];
    float* out = (float*)d_out;

    float *pq, *pk, *pv, *pa;
    __nv_bfloat16 *pah, *pal, *pwh, *pwl;
    cudaGetSymbolAddress((void**)&pq, g_q);
    cudaGetSymbolAddress((void**)&pk, g_k);
    cudaGetSymbolAddress((void**)&pv, g_v);
    cudaGetSymbolAddress((void**)&pa, g_attn);
    cudaGetSymbolAddress((void**)&pah, g_ahi);
    cudaGetSymbolAddress((void**)&pal, g_alo);
    cudaGetSymbolAddress((void**)&pwh, g_whi);
    cudaGetSymbolAddress((void**)&pwl, g_wlo);

    cudaFuncSetAttribute(gemm_tc, cudaFuncAttributeMaxDynamicSharedMemorySize,
                         GEMM_SMEM);
    cudaFuncSetAttribute(flash_attn, cudaFuncAttributeMaxDynamicSharedMemorySize,
                         ATTN_SMEM);

    const size_t nA = (size_t)M_ROWS * E;
    const size_t nW = (size_t)E * E;
    const int cbA = (int)((nA / 4 + 255) / 256);
    const int cbW = (int)((nW / 4 + 255) / 256);

    dim3 gg((M_ROWS + 127) / 128, E / 128, 1);   // 65 x 11

    // hidden states -> bf16 split
    split_bf16<<<cbA, 256>>>(hs, pah, pal, nA);

    // Q
    split_bf16<<<cbW, 256>>>(Wq, pwh, pwl, nW);
    gemm_tc<<<gg, 256, GEMM_SMEM>>>(pah, pal, pwh, pwl, bq, fcos, fsin, pq, M_ROWS, 1);
    // K
    split_bf16<<<cbW, 256>>>(Wk, pwh, pwl, nW);
    gemm_tc<<<gg, 256, GEMM_SMEM>>>(pah, pal, pwh, pwl, bk, fcos, fsin, pk, M_ROWS, 1);
    // V
    split_bf16<<<cbW, 256>>>(Wv, pwh, pwl, nW);
    gemm_tc<<<gg, 256, GEMM_SMEM>>>(pah, pal, pwh, pwl, bv, fcos, fsin, pv, M_ROWS, 0);

    // Attention
    dim3 ga((S + NW * QPW - 1) / (NW * QPW), B * H, 1);  // 33 x 128
    flash_attn<<<ga, 256, ATTN_SMEM>>>(pq, pk, pv, pa);

    // O projection
    split_bf16<<<cbA, 256>>>(pa, pah, pal, nA);
    split_bf16<<<cbW, 256>>>(Wo, pwh, pwl, nW);
    gemm_tc<<<gg, 256, GEMM_SMEM>>>(pah, pal, pwh, pwl, bo, fcos, fsin, out, M_ROWS, 0);
}